// round 17
// baseline (speedup 1.0000x reference)
#include <cuda_runtime.h>
#include <cuda_fp16.h>
#include <cstdint>

#define BB 16
#define LQ 256
#define LK 4096

typedef unsigned long long ull;

// ---------------- device scratch (no allocation allowed) --------------------
// Pre-swizzled 8KB tiles (128B rows, XOR bits[6:4]^=bits[9:7]):
//  g_qh : [b][qt(4)]      tile = 64 q rows  x 64 e           (f16, pre-scaled)
//  g_kh : [b][chunk(64)]  tile = 64 kk rows x 64 e           (f16)
//  g_wth: [b][chunk(64)]  tile = 64 kk rows x [mv(32)|m(32)] (f16, natural)
__device__ __align__(16) __half g_qh [BB * LQ * 64];
__device__ __align__(16) __half g_kh [(long)BB * LK * 64];
__device__ __align__(16) __half g_wth[(long)BB * 64 * LK];
__device__ __align__(16) float  g_part[(long)2 * 16 * 4 * 64 * 256]; // [ks][b][qt][q][256]
__device__ int g_sync[64];   // split-K parity counters (parity flips per launch)

// ---------------- helpers ----------------------------------------------------
__device__ __forceinline__ uint32_t smem_u32(const void* p) {
    uint32_t a;
    asm("{ .reg .u64 t; cvta.to.shared.u64 t, %1; cvt.u32.u64 %0, t; }" : "=r"(a) : "l"(p));
    return a;
}
__device__ __forceinline__ uint32_t f16x2_of(float lo, float hi) {
    uint32_t r; asm("cvt.rn.f16x2.f32 %0, %1, %2;" : "=r"(r) : "f"(hi), "f"(lo)); return r;
}
__device__ __forceinline__ uint32_t ex2x2(uint32_t a) {
    uint32_t r; asm("ex2.approx.f16x2 %0, %1;" : "=r"(r) : "r"(a)); return r;
}
__device__ __forceinline__ ull pack2(float lo, float hi) {
    ull r; asm("mov.b64 %0, {%1,%2};" : "=l"(r) : "f"(lo), "f"(hi)); return r;
}
__device__ __forceinline__ void unpack2(ull v, float& lo, float& hi) {
    asm("mov.b64 {%0,%1}, %2;" : "=f"(lo), "=f"(hi) : "l"(v));
}
__device__ __forceinline__ ull ffma2(ull a, ull b, ull c) {
    ull d; asm("fma.rn.f32x2 %0, %1, %2, %3;" : "=l"(d) : "l"(a), "l"(b), "l"(c));
    return d;
}
__device__ __forceinline__ void ldsm_x4(uint32_t* r, uint32_t a) {
    asm volatile("ldmatrix.sync.aligned.m8n8.x4.shared.b16 {%0,%1,%2,%3}, [%4];"
                 : "=r"(r[0]), "=r"(r[1]), "=r"(r[2]), "=r"(r[3]) : "r"(a));
}
__device__ __forceinline__ void ldsm_x4_t(uint32_t* r, uint32_t a) {
    asm volatile("ldmatrix.sync.aligned.m8n8.x4.trans.shared.b16 {%0,%1,%2,%3}, [%4];"
                 : "=r"(r[0]), "=r"(r[1]), "=r"(r[2]), "=r"(r[3]) : "r"(a));
}
__device__ __forceinline__ void mma_acc(float* d, const uint32_t* a, const uint32_t* b) {
    asm volatile("mma.sync.aligned.m16n8k16.row.col.f32.f16.f16.f32 "
        "{%0,%1,%2,%3}, {%4,%5,%6,%7}, {%8,%9}, {%0,%1,%2,%3};"
        : "+f"(d[0]), "+f"(d[1]), "+f"(d[2]), "+f"(d[3])
        : "r"(a[0]), "r"(a[1]), "r"(a[2]), "r"(a[3]), "r"(b[0]), "r"(b[1]));
}
__device__ __forceinline__ void mma_zro(float* d, const uint32_t* a, const uint32_t* b) {
    asm volatile("mma.sync.aligned.m16n8k16.row.col.f32.f16.f16.f32 "
        "{%0,%1,%2,%3}, {%4,%5,%6,%7}, {%8,%9}, {%10,%10,%10,%10};"
        : "=f"(d[0]), "=f"(d[1]), "=f"(d[2]), "=f"(d[3])
        : "r"(a[0]), "r"(a[1]), "r"(a[2]), "r"(a[3]), "r"(b[0]), "r"(b[1]), "f"(0.0f));
}

#define QSCALE 0.36067376022224085f   // 0.25 * log2(e)
#define SWZ(o) ((o) ^ (((o) >> 3) & 0x70))

// ---- bulk async copy + mbarrier (sm_90 base ISA) ----------------------------
#define MBAR_INIT(mb, n) \
    asm volatile("mbarrier.init.shared.b64 [%0], %1;" :: "r"((uint32_t)(mb)), "r"((uint32_t)(n)) : "memory")
#define EXPECT_TX(mb, bytes) \
    asm volatile("mbarrier.arrive.expect_tx.shared.b64 _, [%0], %1;" \
                 :: "r"((uint32_t)(mb)), "r"((uint32_t)(bytes)) : "memory")
#define MBAR_ARRIVE(mb) \
    asm volatile("mbarrier.arrive.shared.b64 _, [%0];" :: "r"((uint32_t)(mb)) : "memory")
#define BULK_G2S(dst, src, bytes, mb) \
    asm volatile("cp.async.bulk.shared::cluster.global.mbarrier::complete_tx::bytes [%0], [%1], %2, [%3];" \
                 :: "r"((uint32_t)(dst)), "l"(src), "r"((uint32_t)(bytes)), "r"((uint32_t)(mb)) : "memory")
#define MBAR_WAIT(mb, par) do {                                        \
    asm volatile("{\n\t.reg .pred P1;\n\t"                             \
        "WL_%=:\n\t"                                                   \
        "mbarrier.try_wait.parity.shared.b64 P1, [%0], %1;\n\t"        \
        "@P1 bra.uni WD_%=;\n\t"                                       \
        "bra.uni WL_%=;\n\t"                                           \
        "WD_%=:\n\t}"                                                  \
        :: "r"((uint32_t)(mb)), "r"((uint32_t)(par)) : "memory");      \
} while (0)

// ---------------- fused prep: proj-q | proj-k | Wt build --------------------
// grid 1600: [0,64) proj q, [64,1088) proj k, [1088,1600) wt (2 chunks each)
// Proj inputs read DIRECTLY from global (L1-broadcast across the 16 threads
// sharing each row); only W is staged. SMEM 16KB -> 8 CTA/SM.
__global__ void __launch_bounds__(256) prep_kernel(
    const float* __restrict__ qin, const float* __restrict__ kin,
    const float* __restrict__ v, const int* __restrict__ m,
    const float* __restrict__ Wq, const float* __restrict__ bq,
    const float* __restrict__ Wk, const float* __restrict__ bk)
{
    __shared__ __align__(16) float Wsh[64 * 64];   // 16KB
    const int bid = blockIdx.x, t = threadIdx.x;

    if (bid < 1088) {
        const int isq = (bid < 64);
        const float* in   = isq ? qin : kin;
        const float* W    = isq ? Wq : Wk;
        const float* bias = isq ? bq : bk;
        const float scale = isq ? QSCALE : 1.0f;
        char* otile = (char*)(isq ? g_qh : g_kh) + (long)(isq ? bid : bid - 64) * 8192;
        const long row0 = (long)(isq ? bid : bid - 64) * 64;
        #pragma unroll
        for (int i = t; i < 1024; i += 256) ((float4*)Wsh)[i] = ((const float4*)W)[i];
        __syncthreads();

        const int e0 = (t & 15) * 4;
        const int rb = (t >> 4) * 4;
        const float4* r0p = (const float4*)(in + (row0 + rb + 0) * 64);
        const float4* r1p = (const float4*)(in + (row0 + rb + 1) * 64);
        const float4* r2p = (const float4*)(in + (row0 + rb + 2) * 64);
        const float4* r3p = (const float4*)(in + (row0 + rb + 3) * 64);
        float4 bv = *(const float4*)&bias[e0];
        ull a01 = pack2(bv.x, bv.y), a23 = pack2(bv.z, bv.w);
        ull acc[4][2];
        #pragma unroll
        for (int r = 0; r < 4; r++) { acc[r][0] = a01; acc[r][1] = a23; }
        // per-output j sequence identical to prior rounds -> bit-identical results
        #pragma unroll 4
        for (int j4 = 0; j4 < 64; j4 += 4) {
            float4 iv0 = r0p[j4 >> 2];
            float4 iv1 = r1p[j4 >> 2];
            float4 iv2 = r2p[j4 >> 2];
            float4 iv3 = r3p[j4 >> 2];
            #pragma unroll
            for (int jj = 0; jj < 4; jj++) {
                ulonglong2 wv = *(const ulonglong2*)&Wsh[(j4 + jj) * 64 + e0];
                float i0 = (jj == 0) ? iv0.x : (jj == 1) ? iv0.y : (jj == 2) ? iv0.z : iv0.w;
                float i1 = (jj == 0) ? iv1.x : (jj == 1) ? iv1.y : (jj == 2) ? iv1.z : iv1.w;
                float i2 = (jj == 0) ? iv2.x : (jj == 1) ? iv2.y : (jj == 2) ? iv2.z : iv2.w;
                float i3 = (jj == 0) ? iv3.x : (jj == 1) ? iv3.y : (jj == 2) ? iv3.z : iv3.w;
                ull d0 = pack2(i0, i0), d1 = pack2(i1, i1);
                ull d2 = pack2(i2, i2), d3 = pack2(i3, i3);
                acc[0][0] = ffma2(d0, wv.x, acc[0][0]);
                acc[0][1] = ffma2(d0, wv.y, acc[0][1]);
                acc[1][0] = ffma2(d1, wv.x, acc[1][0]);
                acc[1][1] = ffma2(d1, wv.y, acc[1][1]);
                acc[2][0] = ffma2(d2, wv.x, acc[2][0]);
                acc[2][1] = ffma2(d2, wv.y, acc[2][1]);
                acc[3][0] = ffma2(d3, wv.x, acc[3][0]);
                acc[3][1] = ffma2(d3, wv.y, acc[3][1]);
            }
        }
        #pragma unroll
        for (int r = 0; r < 4; r++) {
            float v0, v1, v2, v3;
            unpack2(acc[r][0], v0, v1);
            unpack2(acc[r][1], v2, v3);
            uint2 u;
            u.x = f16x2_of(v0 * scale, v1 * scale);
            u.y = f16x2_of(v2 * scale, v3 * scale);
            uint32_t off = SWZ((uint32_t)(rb + r) * 128 + e0 * 2);
            *(uint2*)(otile + off) = u;
        }
    } else {
        // Wt build, natural layout: tile row kk = [mv(32 f16) | m(32 f16)]
        const int id = bid - 1088;
        const int b = id >> 5, kt = id & 31;
        const long base = ((long)b * LK + kt * 128) * 32;
        char* wt0 = (char*)g_wth + ((long)b * 64 + kt * 2) * 8192;
        const float4* v4 = (const float4*)(v + base);
        const int4*   m4p = (const int4*)(m + base);
        #pragma unroll
        for (int i = t; i < 1024; i += 256) {
            int kk = i >> 3, d4 = i & 7;
            float4 vv = v4[i];
            int4   mm = m4p[i];
            float m0 = (float)mm.x, m1 = (float)mm.y, m2 = (float)mm.z, m3 = (float)mm.w;
            uint2 umv, um;
            umv.x = f16x2_of(m0 * vv.x, m1 * vv.y);
            umv.y = f16x2_of(m2 * vv.z, m3 * vv.w);
            um.x  = f16x2_of(m0, m1);
            um.y  = f16x2_of(m2, m3);
            char* tile = wt0 + (long)(kk >> 6) * 8192;
            uint32_t row = (uint32_t)(kk & 63) * 128;
            *(uint2*)(tile + SWZ(row + d4 * 8))      = umv;
            *(uint2*)(tile + SWZ(row + 64 + d4 * 8)) = um;
        }
    }
}

// ---------------- main fused attention + split-K finalize (R16 verbatim) ----
// grid (4 qt, 16 b, 2 ks) = 128 CTAs, 256 thr = 8 warps: warp = (h = w&3, s = w>>2).
// Per-stage EMPTY mbarriers (count=8) instead of per-chunk __syncthreads.
__global__ void __launch_bounds__(256, 1) attn_kernel(
    const float* __restrict__ Wo, const float* __restrict__ bo,
    float* __restrict__ out)
{
    extern __shared__ __align__(16) char smraw[];
    const uint32_t base = smem_u32(smraw);
    const uint32_t sb = (base + 1023) & ~1023u;
    char* shb = smraw + (sb - base);
    const uint32_t mb0 = sb + 73728;        // full[0..3] @+0..31, q @+32, empty[0..3] @+40..71

    const int t = threadIdx.x, l = t & 31, w = t >> 5;
    const int h = w & 3, s = w >> 2;
    const int qt = blockIdx.x, b = blockIdx.y, ks = blockIdx.z;

    const char* qtile = (const char*)g_qh  + ((long)(b * 4  + qt)) * 8192;
    const char* ktile = (const char*)g_kh  + ((long)(b * 64 + ks * 32)) * 8192;
    const char* wtile = (const char*)g_wth + ((long)(b * 64 + ks * 32)) * 8192;

    if (t == 0) {
        #pragma unroll
        for (int i = 0; i < 5; i++) MBAR_INIT(mb0 + i * 8, 1);
        #pragma unroll
        for (int i = 0; i < 4; i++) MBAR_INIT(mb0 + 40 + i * 8, 8);  // empty: 8 warps
    }
    __syncthreads();
    if (t == 0) {
        asm volatile("fence.proxy.async.shared::cta;" ::: "memory");
        EXPECT_TX(mb0 + 32, 8192);
        BULK_G2S(sb, qtile, 8192, mb0 + 32);
        #pragma unroll
        for (int c = 0; c < 3; c++) {
            EXPECT_TX(mb0 + c * 8, 16384);
            BULK_G2S(sb + 8192 + c * 16384,        ktile + (long)c * 8192, 8192, mb0 + c * 8);
            BULK_G2S(sb + 8192 + c * 16384 + 8192, wtile + (long)c * 8192, 8192, mb0 + c * 8);
        }
    }

    const int li = l & 7, m4 = l >> 3;
    const uint32_t lix4 = (uint32_t)li << 4;
    const uint32_t kRowBase = (uint32_t)(s * 32 + (m4 >> 1) * 8 + li) * 128
                            + (((uint32_t)(h * 32 + (m4 & 1) * 16)) ^ lix4);
    const uint32_t wRowBase = (uint32_t)(s * 32 + (m4 & 1) * 8 + li) * 128;
    uint32_t wColB[4];
    #pragma unroll
    for (int p = 0; p < 4; p++)
        wColB[p] = ((uint32_t)(p * 32 + (m4 >> 1) * 16)) ^ lix4;

    MBAR_WAIT(mb0 + 32, 0);
    uint32_t aq[4][4];
    {
        const int quad = l >> 3;
        #pragma unroll
        for (int mt = 0; mt < 4; mt++) {
            const uint32_t arow = (uint32_t)(mt * 16 + (quad & 1) * 8 + li) * 128;
            const uint32_t acol = ((uint32_t)(h * 32 + (quad >> 1) * 16)) ^ lix4;
            ldsm_x4(aq[mt], sb + arow + acol);
        }
    }

    float O[4][8][4];
    #pragma unroll
    for (int mt = 0; mt < 4; mt++)
        #pragma unroll
        for (int nt = 0; nt < 8; nt++)
            #pragma unroll
            for (int i = 0; i < 4; i++) O[mt][nt][i] = 0.0f;

    for (int c = 0; c < 32; c++) {
        MBAR_WAIT(mb0 + (c & 3) * 8, (c >> 2) & 1);   // chunk c data resident
        if (t == 0 && c + 3 < 32) {
            const int j = c + 3, st = j & 3;
            if (j >= 4) MBAR_WAIT(mb0 + 40 + st * 8, ((j - 4) >> 2) & 1);
            EXPECT_TX(mb0 + st * 8, 16384);
            BULK_G2S(sb + 8192 + st * 16384,        ktile + (long)j * 8192, 8192, mb0 + st * 8);
            BULK_G2S(sb + 8192 + st * 16384 + 8192, wtile + (long)j * 8192, 8192, mb0 + st * 8);
        }

        const uint32_t KBp = sb + 8192 + (uint32_t)(c & 3) * 16384, WBp = KBp + 8192;

        // GEMM1 + exp: warp covers kk [s*32, s*32+32) of this chunk
        uint32_t E[4][2][4];
        #pragma unroll
        for (int j = 0; j < 2; j++) {
            uint32_t kf[4];
            ldsm_x4(kf, KBp + kRowBase + (uint32_t)j * 2048);
            #pragma unroll
            for (int mt = 0; mt < 4; mt++) {
                float s0[4], s1[4];
                mma_zro(s0, aq[mt], kf);
                mma_zro(s1, aq[mt], kf + 2);
                E[mt][j][0] = ex2x2(f16x2_of(s0[0], s0[1]));
                E[mt][j][1] = ex2x2(f16x2_of(s0[2], s0[3]));
                E[mt][j][2] = ex2x2(f16x2_of(s1[0], s1[1]));
                E[mt][j][3] = ex2x2(f16x2_of(s1[2], s1[3]));
            }
        }

        // GEMM2: O += E . W   (W rows=kk, cols=d; trans-ldmatrix)
        #pragma unroll
        for (int j = 0; j < 2; j++) {
            const uint32_t wj = WBp + wRowBase + (uint32_t)j * 2048;
            #pragma unroll
            for (int p = 0; p < 4; p++) {
                uint32_t wf[4];
                ldsm_x4_t(wf, wj + wColB[p]);
                #pragma unroll
                for (int mt = 0; mt < 4; mt++) {
                    mma_acc(O[mt][2 * p],     E[mt][j], wf);
                    mma_acc(O[mt][2 * p + 1], E[mt][j], wf + 2);
                }
            }
        }

        if (l == 0) MBAR_ARRIVE(mb0 + 40 + (c & 3) * 8);
    }
    __syncthreads();   // all warps past the loop before stages are reused

    // ---- reduce kk-halves (s=1 -> SMEM, s=0 adds), write partials ----------
    float* red = (float*)(shb + 8192);   // [h][q 64][col 64], xor-swizzled
    #define RIDX(q, col) ((q) * 64 + ((col) ^ (((q) & 3) << 3)))
    if (s == 1) {
        #pragma unroll
        for (int mt = 0; mt < 4; mt++)
            #pragma unroll
            for (int nt = 0; nt < 8; nt++)
                #pragma unroll
                for (int i = 0; i < 4; i++) {
                    int q = mt * 16 + (l >> 2) + ((i >> 1) & 1) * 8;
                    int col = nt * 8 + 2 * (l & 3) + (i & 1);
                    red[h * 4096 + RIDX(q, col)] = O[mt][nt][i];
                }
    }
    __syncthreads();
    if (s == 0) {
        float* P = g_part + ((((long)ks * 16 + b) * 4 + qt) << 14);
        #pragma unroll
        for (int mt = 0; mt < 4; mt++)
            #pragma unroll
            for (int nt = 0; nt < 8; nt++) {
                #pragma unroll
                for (int i = 0; i < 4; i++) {
                    int q = mt * 16 + (l >> 2) + ((i >> 1) & 1) * 8;
                    int col = nt * 8 + 2 * (l & 3) + (i & 1);
                    O[mt][nt][i] += red[h * 4096 + RIDX(q, col)];
                }
                int q0 = mt * 16 + (l >> 2);
                int col = h * 64 + nt * 8 + 2 * (l & 3);
                *(float2*)(P + (long)q0 * 256 + col)       = make_float2(O[mt][nt][0], O[mt][nt][1]);
                *(float2*)(P + (long)(q0 + 8) * 256 + col) = make_float2(O[mt][nt][2], O[mt][nt][3]);
            }
    }
    __syncthreads();

    // ---- split-K finalize: second arriving CTA of each (b,qt) does the tail --
    if (t == 0) {
        __threadfence();
        int old = atomicAdd(&g_sync[b * 4 + qt], 1);
        *(volatile int*)shb = (old & 1);
    }
    __syncthreads();
    if (*(volatile int*)shb == 0) return;

    const float* P0 = g_part + ((((long)0 * 16 + b) * 4 + qt) << 14);
    const float* P1 = g_part + ((((long)1 * 16 + b) * 4 + qt) << 14);
    float* X = (float*)(shb + 8192);     // [64][132]
    #pragma unroll
    for (int f4 = t; f4 < 2048; f4 += 256) {
        int q = f4 >> 5, c4 = f4 & 31;
        int hh = c4 >> 3, d4 = c4 & 7;
        long o = (long)q * 256 + hh * 64 + d4 * 4;
        float4 n0 = *(const float4*)(P0 + o);
        float4 n1 = *(const float4*)(P1 + o);
        float4 d0 = *(const float4*)(P0 + o + 32);
        float4 d1 = *(const float4*)(P1 + o + 32);
        float* xr = X + q * 132 + hh * 32 + d4 * 4;
        xr[0] = __fdividef(n0.x + n1.x, d0.x + d1.x);
        xr[1] = __fdividef(n0.y + n1.y, d0.y + d1.y);
        xr[2] = __fdividef(n0.z + n1.z, d0.z + d1.z);
        xr[3] = __fdividef(n0.w + n1.w, d0.w + d1.w);
    }
    __syncthreads();

    const int q = t >> 2, lat0 = (t & 3) * 8;
    float acc[8];
    #pragma unroll
    for (int i = 0; i < 8; i++) acc[i] = bo[lat0 + i];
    #pragma unroll 8
    for (int j = 0; j < 128; j++) {
        float xv = X[q * 132 + j];
        float4 w0 = *(const float4*)&Wo[j * 32 + lat0];
        float4 w1 = *(const float4*)&Wo[j * 32 + lat0 + 4];
        acc[0] += xv * w0.x; acc[1] += xv * w0.y; acc[2] += xv * w0.z; acc[3] += xv * w0.w;
        acc[4] += xv * w1.x; acc[5] += xv * w1.y; acc[6] += xv * w1.z; acc[7] += xv * w1.w;
    }
    float* op = out + ((long)(b * LQ + qt * 64 + q)) * 32 + lat0;
    *(float4*)op       = make_float4(acc[0], acc[1], acc[2], acc[3]);
    *(float4*)(op + 4) = make_float4(acc[4], acc[5], acc[6], acc[7]);
}

// ---------------- launch ------------------------------------------------------
extern "C" void kernel_launch(void* const* d_in, const int* in_sizes, int n_in,
                              void* d_out, int out_size)
{
    const float* query = (const float*)d_in[0];
    const float* key   = (const float*)d_in[1];
    const float* value = (const float*)d_in[2];
    const int*   mask  = (const int*)  d_in[3];
    const float* Wq    = (const float*)d_in[4];
    const float* bq    = (const float*)d_in[5];
    const float* Wk    = (const float*)d_in[6];
    const float* bk    = (const float*)d_in[7];
    const float* Wo    = (const float*)d_in[8];
    const float* bo    = (const float*)d_in[9];
    float* out = (float*)d_out;
    (void)in_sizes; (void)n_in; (void)out_size;

    const int attn_smem = 73728 + 128 + 1024;   // Q + 4 stages + mbars + align slack
    cudaFuncSetAttribute(attn_kernel, cudaFuncAttributeMaxDynamicSharedMemorySize, attn_smem);

    prep_kernel<<<1600, 256>>>(query, key, value, mask, Wq, bq, Wk, bk);
    dim3 grid(4, BB, 2);
    attn_kernel<<<grid, 256, attn_smem>>>(Wo, bo, out);
}